// round 9
// baseline (speedup 1.0000x reference)
#include <cuda_runtime.h>

#define B_   256
#define T_   1000
#define H_   256
#define DIN  64
#define DOUT 64
#define NC_  10
#define R_   4
#define G_   (B_ / R_)          /* 64 CTAs */
#define NTHR 256
#define STEPS (T_ - 1)
#define LOGITS_OFF ((size_t)B_ * (size_t)T_ * (size_t)DOUT)

#define KT        32                      /* k-rows per weight tile        */
#define STAGES    3                       /* smem ring depth               */
#define TILE_BYTES (KT * H_ * 8)          /* 65536 B (float2 rows)         */
#define TILES_PER_STEP 16                 /* 8 A-tiles + 8 B-tiles         */
#define NT_TOTAL  (TILES_PER_STEP * STEPS)

// ---------------------------------------------------------------------------
// Device scratch: fused + transposed weights (recomputed every call).
// ---------------------------------------------------------------------------
__device__ float2 g_AT [H_ + 1][H_];  // [k][j] = {Af[j][k], Ag[j][k]}  (Af=Wf1@W_in, Ag=Wg1@Wn)
__device__ float2 g_cfg[H_];          // {Wf1@b_in+bf1, Wg1@bn+bg1}
__device__ float2 g_W2T[H_][H_];      // [k][n] = {Wf2[n][k], Wg2[n][k]}
__device__ float2 g_b2 [H_];          // {bf2[n], bg2[n]}

// ---------------------------------------------------------------------------
// Packed fp32x2 + async helpers.
// ---------------------------------------------------------------------------
__device__ __forceinline__ void ffma2(unsigned long long& acc,
                                      unsigned long long a, unsigned long long b) {
    asm("fma.rn.f32x2 %0, %1, %2, %0;" : "+l"(acc) : "l"(a), "l"(b));
}
__device__ __forceinline__ unsigned long long pack2(float lo, float hi) {
    unsigned long long r;
    asm("mov.b64 %0, {%1, %2};" : "=l"(r)
        : "r"(__float_as_uint(lo)), "r"(__float_as_uint(hi)));
    return r;
}
__device__ __forceinline__ float lo2(unsigned long long v) {
    return __uint_as_float((unsigned)(v & 0xffffffffull));
}
__device__ __forceinline__ float hi2(unsigned long long v) {
    return __uint_as_float((unsigned)(v >> 32));
}
__device__ __forceinline__ float lipswish(float x) {
    return 0.909f * x / (1.0f + expf(-x));
}
__device__ __forceinline__ unsigned long long ld_u64(const void* p) {
    return *reinterpret_cast<const unsigned long long*>(p);
}
__device__ __forceinline__ unsigned smem_u32(const void* p) {
    return (unsigned)__cvta_generic_to_shared(p);
}
__device__ __forceinline__ void mbar_init(unsigned mbar, unsigned cnt) {
    asm volatile("mbarrier.init.shared.b64 [%0], %1;" :: "r"(mbar), "r"(cnt) : "memory");
}
__device__ __forceinline__ void mbar_expect(unsigned mbar, unsigned bytes) {
    asm volatile("mbarrier.arrive.expect_tx.shared.b64 _, [%0], %1;"
                 :: "r"(mbar), "r"(bytes) : "memory");
}
__device__ __forceinline__ void bulk_cp(unsigned dst, const void* src,
                                        unsigned bytes, unsigned mbar) {
    asm volatile("cp.async.bulk.shared::cluster.global.mbarrier::complete_tx::bytes "
                 "[%0], [%1], %2, [%3];"
                 :: "r"(dst), "l"(src), "r"(bytes), "r"(mbar) : "memory");
}
__device__ __forceinline__ void fence_async() {
    asm volatile("fence.proxy.async.shared::cta;" ::: "memory");
}
__device__ __forceinline__ void mbar_wait_acq(unsigned addr, unsigned parity) {
    unsigned done;
    asm volatile("{\n\t.reg .pred p;\n\t"
        "mbarrier.try_wait.parity.acquire.cta.shared::cta.b64 p, [%1], %2, 0x989680;\n\t"
        "selp.b32 %0, 1, 0, p;\n\t}"
        : "=r"(done) : "r"(addr), "r"(parity) : "memory");
    while (!done) {
        asm volatile("{\n\t.reg .pred p;\n\t"
            "mbarrier.try_wait.parity.acquire.cta.shared::cta.b64 p, [%1], %2, 0x989680;\n\t"
            "selp.b32 %0, 1, 0, p;\n\t}"
            : "=r"(done) : "r"(addr), "r"(parity) : "memory");
    }
}

// ---------------------------------------------------------------------------
// Prep 1: fuse the two linear pairs. Blocks 0..H_ -> column k; block H_+1 -> bias.
// ---------------------------------------------------------------------------
__global__ __launch_bounds__(NTHR) void sde_prep_fuse(
    const float* __restrict__ W_in, const float* __restrict__ b_in,
    const float* __restrict__ Wf1,  const float* __restrict__ bf1,
    const float* __restrict__ Wn,   const float* __restrict__ bn,
    const float* __restrict__ Wg1,  const float* __restrict__ bg1)
{
    __shared__ float cin[H_], cn[H_];
    const int j = threadIdx.x;
    const int k = blockIdx.x;
    if (k < H_ + 1) { cin[j] = W_in[j * (H_ + 1) + k]; cn[j] = Wn[j * (H_ + 1) + k]; }
    else            { cin[j] = b_in[j];                cn[j]  = bn[j]; }
    __syncthreads();
    const float* wf1r = Wf1 + (size_t)j * H_;
    const float* wg1r = Wg1 + (size_t)j * H_;
    float af = 0.f, ag = 0.f;
#pragma unroll 8
    for (int m = 0; m < H_; m++) {
        af = fmaf(wf1r[m], cin[m], af);
        ag = fmaf(wg1r[m], cn[m],  ag);
    }
    if (k < H_ + 1) g_AT[k][j] = make_float2(af, ag);
    else            g_cfg[j]   = make_float2(af + bf1[j], ag + bg1[j]);
}

// ---------------------------------------------------------------------------
// Prep 2: transpose + interleave second-layer weights.
// ---------------------------------------------------------------------------
__global__ __launch_bounds__(NTHR) void sde_prep_w2(
    const float* __restrict__ Wf2, const float* __restrict__ bf2,
    const float* __restrict__ Wg2, const float* __restrict__ bg2)
{
    const int n = threadIdx.x;
    const int k = blockIdx.x;
    g_W2T[k][n] = make_float2(Wf2[(size_t)n * H_ + k], Wg2[(size_t)n * H_ + k]);
    if (k == 0) g_b2[n] = make_float2(bf2[n], bg2[n]);
}

// ---------------------------------------------------------------------------
// Dynamic shared layout (~225 KB)
// ---------------------------------------------------------------------------
struct Smem {
    float2 w[STAGES][KT][H_];          // weight ring: 196608 B
    float2 yd [R_][H_];                // {y_r, y_r} duplicated (FFMA2 broadcast)
    float2 y01[H_];                    // {y_row0, y_row1}
    float2 y23[H_];                    // {y_row2, y_row3}
    float2 hfg[R_][H_];                // {hf, hg}
    float4 part[4][DOUT];              // pred partials per k-quarter
    float  zf[R_][H_];
    float  tm[T_];
    float  x0[R_][DIN];
    int    len[R_];
    unsigned long long mbar[STAGES];
};

// ---------------------------------------------------------------------------
// Main persistent kernel: 64 CTAs x 256 threads; each CTA runs all 999 steps
// for 4 independent batch rows. Weights streamed via cp.async.bulk ring.
// ---------------------------------------------------------------------------
__global__ __launch_bounds__(NTHR, 1) void sde_main(
    const float* __restrict__ coeffs, const float* __restrict__ times,
    const int*   __restrict__ mask,   const float* __restrict__ noise,
    const float* __restrict__ W0,     const float* __restrict__ b0,
    const float* __restrict__ Wd,     const float* __restrict__ bd,
    const float* __restrict__ Wc,     const float* __restrict__ bc,
    float* __restrict__ out)
{
    extern __shared__ char smem_raw[];
    Smem* sm = reinterpret_cast<Smem*>(smem_raw);

    const int tid  = threadIdx.x;
    const int row0 = blockIdx.x * R_;
    const int n    = tid;

    const unsigned sw_base = smem_u32(&sm->w[0][0][0]);
    const unsigned mb_base = smem_u32(&sm->mbar[0]);

    auto tile_src = [&](int t) -> const void* {
        const int idx = t & 15;
        return (idx < 8)
            ? (const void*)((const char*)&g_AT[1][0]  + (size_t)idx * TILE_BYTES)
            : (const void*)((const char*)&g_W2T[0][0] + (size_t)(idx - 8) * TILE_BYTES);
    };

    // ---- init smem state + start the weight pipeline ----
    if (tid < R_) sm->len[tid] = 0;
    for (int t = tid; t < T_; t += NTHR) sm->tm[t] = times[t];
    if (tid < DIN) {
#pragma unroll
        for (int r = 0; r < R_; r++)
            sm->x0[r][tid] = coeffs[(size_t)(row0 + r) * (size_t)(T_ - 1) * (4 * DIN) + tid];
    }
    if (tid == 0) {
#pragma unroll
        for (int s = 0; s < STAGES; s++) mbar_init(mb_base + s * 8, 1);
    }
    __syncthreads();
    if (tid == 0) {
        fence_async();
#pragma unroll
        for (int t = 0; t < STAGES; t++) {
            mbar_expect(mb_base + t * 8, TILE_BYTES);
            bulk_cp(sw_base + t * TILE_BYTES, tile_src(t), TILE_BYTES, mb_base + t * 8);
        }
    }
    // mask lengths
    {
        int acc[R_] = {0, 0, 0, 0};
        for (int t = tid; t < T_; t += NTHR) {
#pragma unroll
            for (int r = 0; r < R_; r++) acc[r] += mask[(size_t)(row0 + r) * T_ + t];
        }
#pragma unroll
        for (int r = 0; r < R_; r++) atomicAdd(&sm->len[r], acc[r]);
    }
    __syncthreads();
    int lastidx[R_];
#pragma unroll
    for (int r = 0; r < R_; r++) lastidx[r] = sm->len[r] - 1;

    // ---- constants held in registers for the whole scan ----
    const float2 a0  = g_AT[0][tid];
    const unsigned long long a0p = pack2(a0.x, a0.y);
    const float2 ccf = g_cfg[tid];
    const float2 cb2 = g_b2[tid];

    // ---- y0 = x0 @ W0^T + b0 ----
    float y[R_];
    {
        const float* w0r = W0 + (size_t)n * DIN;
        const float  bb  = b0[n];
#pragma unroll
        for (int r = 0; r < R_; r++) {
            float a = bb;
#pragma unroll 16
            for (int d = 0; d < DIN; d++) a = fmaf(sm->x0[r][d], w0r[d], a);
            y[r] = a;
        }
    }
    float zfin[R_];
#pragma unroll
    for (int r = 0; r < R_; r++) zfin[r] = y[r];   // covers lastidx == 0

    // ---- Wd slice in registers: thread (pm = tid&63, pq = tid>>6) ----
    const int pm = tid & 63;
    const int pq = tid >> 6;
    float wd[64];
    {
        const float* wdr = Wd + (size_t)pm * H_ + pq * 64;
#pragma unroll
        for (int kk = 0; kk < 64; kk++) wd[kk] = wdr[kk];
    }
    const float bdv = bd[pm];

    // ---- publish y for index 0 ----
    float t_cur = sm->tm[0];
    sm->y01[n] = make_float2(y[0], y[1]);
    sm->y23[n] = make_float2(y[2], y[3]);
#pragma unroll
    for (int r = 0; r < R_; r++) sm->yd[r][n] = make_float2(y[r], y[r]);
    __syncthreads();

    // ---- predicted[b][idx][:] = y @ Wd^T + bd ----
    auto do_pred = [&](int idx) {
        unsigned long long a01 = 0ull, a23 = 0ull;
        const int kbase = pq * 64;
#pragma unroll
        for (int kk = 0; kk < 64; kk++) {
            const unsigned long long wp = pack2(wd[kk], wd[kk]);
            ffma2(a01, ld_u64(&sm->y01[kbase + kk]), wp);
            ffma2(a23, ld_u64(&sm->y23[kbase + kk]), wp);
        }
        sm->part[pq][pm] = make_float4(lo2(a01), hi2(a01), lo2(a23), hi2(a23));
        __syncthreads();
        {
            const int r2 = tid >> 6;
            float v = bdv;
#pragma unroll
            for (int qq = 0; qq < 4; qq++)
                v += reinterpret_cast<const float*>(&sm->part[qq][pm])[r2];
            out[(size_t)(row0 + r2) * T_ * DOUT + (size_t)idx * DOUT + pm] = v;
        }
    };

    do_pred(0);

    // ======================= main scan: 999 steps =======================
    int tglob = 0;        // global tile counter
    int s     = 0;        // ring stage = tglob % 3
    unsigned par = 0;     // parity = (tglob / 3) & 1

    for (int i = 0; i < STEPS; i++) {
        // ---- phase A: pre-act = A @ [t; y] (thread = output j), tiles 0..7 ----
        unsigned long long accA[R_];
        {
            const unsigned long long tt = pack2(t_cur, t_cur);
#pragma unroll
            for (int r = 0; r < R_; r++) { accA[r] = 0ull; ffma2(accA[r], tt, a0p); }
        }
#pragma unroll 1
        for (int a = 0; a < 8; a++) {
            mbar_wait_acq(mb_base + s * 8, par);
            const unsigned long long* wrow =
                reinterpret_cast<const unsigned long long*>(&sm->w[s][0][0]);
            const int kb = a * KT;
#pragma unroll 8
            for (int kk = 0; kk < KT; kk++) {
                const unsigned long long w = wrow[kk * H_ + tid];
#pragma unroll
                for (int r = 0; r < R_; r++)
                    ffma2(accA[r], ld_u64(&sm->yd[r][kb + kk]), w);
            }
            __syncthreads();
            if (tid == 0 && tglob + 3 < NT_TOTAL) {
                fence_async();
                mbar_expect(mb_base + s * 8, TILE_BYTES);
                bulk_cp(sw_base + s * TILE_BYTES, tile_src(tglob + 3), TILE_BYTES,
                        mb_base + s * 8);
            }
            tglob++; s++; if (s == STAGES) { s = 0; par ^= 1; }
        }
        // bias + lipswish -> hfg
#pragma unroll
        for (int r = 0; r < R_; r++) {
            const float hf = lipswish(lo2(accA[r]) + ccf.x);
            const float hg = lipswish(hi2(accA[r]) + ccf.y);
            sm->hfg[r][tid] = make_float2(hf, hg);
        }
        // prefetch noise for this step
        float eps[R_];
        {
            const float* np = noise + ((size_t)i * B_ + row0) * H_ + n;
#pragma unroll
            for (int r = 0; r < R_; r++) eps[r] = __ldg(np + (size_t)r * H_);
        }
        __syncthreads();

        // ---- phase B: f,g = h @ W2 (thread = output n), tiles 8..15 ----
        unsigned long long accB[R_] = {0ull, 0ull, 0ull, 0ull};
#pragma unroll 1
        for (int b = 0; b < 8; b++) {
            mbar_wait_acq(mb_base + s * 8, par);
            const unsigned long long* wrow =
                reinterpret_cast<const unsigned long long*>(&sm->w[s][0][0]);
            const int kb = b * KT;
#pragma unroll 8
            for (int kk = 0; kk < KT; kk++) {
                const unsigned long long w = wrow[kk * H_ + tid];
#pragma unroll
                for (int r = 0; r < R_; r++)
                    ffma2(accB[r], ld_u64(&sm->hfg[r][kb + kk]), w);
            }
            __syncthreads();
            if (tid == 0 && tglob + 3 < NT_TOTAL) {
                fence_async();
                mbar_expect(mb_base + s * 8, TILE_BYTES);
                bulk_cp(sw_base + s * TILE_BYTES, tile_src(tglob + 3), TILE_BYTES,
                        mb_base + s * 8);
            }
            tglob++; s++; if (s == STAGES) { s = 0; par ^= 1; }
        }
        // ---- y update ----
        {
            const float t_next = sm->tm[i + 1];
            const float dt = t_next - t_cur;
            const float sd = sqrtf(dt);
#pragma unroll
            for (int r = 0; r < R_; r++) {
                const float f = lo2(accB[r]) + cb2.x;
                const float g = hi2(accB[r]) + cb2.y;
                y[r] = fmaf(f, dt, fmaf(g, sd * eps[r], y[r]));
                if (i + 1 == lastidx[r]) zfin[r] = y[r];
            }
            t_cur = t_next;
        }
        // publish y for index i+1
        sm->y01[n] = make_float2(y[0], y[1]);
        sm->y23[n] = make_float2(y[2], y[3]);
#pragma unroll
        for (int r = 0; r < R_; r++) sm->yd[r][n] = make_float2(y[r], y[r]);
        __syncthreads();

        do_pred(i + 1);
    }

    // ---- logits = z_final @ Wc^T + bc ----
#pragma unroll
    for (int r = 0; r < R_; r++) sm->zf[r][n] = zfin[r];
    __syncthreads();
    if (tid < R_ * NC_) {
        const int r = tid / NC_;
        const int c = tid % NC_;
        const float* wcr = Wc + (size_t)c * H_;
        float a = bc[c];
#pragma unroll 8
        for (int k = 0; k < H_; k++) a = fmaf(sm->zf[r][k], wcr[k], a);
        out[LOGITS_OFF + (size_t)(row0 + r) * NC_ + c] = a;
    }
}

// ---------------------------------------------------------------------------
// Launch: two prep kernels, then the persistent scan. Stream-0 only,
// allocation-free, graph-capturable.
// ---------------------------------------------------------------------------
extern "C" void kernel_launch(void* const* d_in, const int* in_sizes, int n_in,
                              void* d_out, int out_size) {
    const float* coeffs = (const float*)d_in[0];
    const float* times  = (const float*)d_in[1];
    const int*   mask   = (const int*)  d_in[2];
    const float* noise  = (const float*)d_in[3];
    const float* W_in   = (const float*)d_in[4];
    const float* b_in   = (const float*)d_in[5];
    const float* Wf1    = (const float*)d_in[6];
    const float* bf1    = (const float*)d_in[7];
    const float* Wf2    = (const float*)d_in[8];
    const float* bf2    = (const float*)d_in[9];
    const float* Wn     = (const float*)d_in[10];
    const float* bn     = (const float*)d_in[11];
    const float* Wg1    = (const float*)d_in[12];
    const float* bg1    = (const float*)d_in[13];
    const float* Wg2    = (const float*)d_in[14];
    const float* bg2    = (const float*)d_in[15];
    const float* W0     = (const float*)d_in[16];
    const float* b0     = (const float*)d_in[17];
    const float* Wd     = (const float*)d_in[18];
    const float* bd     = (const float*)d_in[19];
    const float* Wc     = (const float*)d_in[20];
    const float* bc     = (const float*)d_in[21];
    float* out = (float*)d_out;

    const int smem_bytes = (int)sizeof(Smem);
    cudaFuncSetAttribute(sde_main, cudaFuncAttributeMaxDynamicSharedMemorySize,
                         smem_bytes);

    sde_prep_fuse<<<H_ + 2, NTHR>>>(W_in, b_in, Wf1, bf1, Wn, bn, Wg1, bg1);
    sde_prep_w2  <<<H_,     NTHR>>>(Wf2, bf2, Wg2, bg2);
    sde_main     <<<G_, NTHR, smem_bytes>>>(coeffs, times, mask, noise,
                                            W0, b0, Wd, bd, Wc, bc, out);
}

// round 10
// speedup vs baseline: 1.1912x; 1.1912x over previous
#include <cuda_runtime.h>

#define B_   256
#define T_   1000
#define H_   256
#define DIN  64
#define DOUT 64
#define NC_  10
#define R_   4
#define G_   (B_ / R_)          /* 64 CTAs */
#define NTHR 512
#define STEPS (T_ - 1)
#define LOGITS_OFF ((size_t)B_ * (size_t)T_ * (size_t)DOUT)
#define KP   128                /* k-pairs per phase (256 k / 2) */

// ---------------------------------------------------------------------------
// Device scratch (recomputed every call).
// g_WA[k2][j] = {Af[j][1+2k2], Ag[j][1+2k2], Af[j][2+2k2], Ag[j][2+2k2]}
// g_WB[k2][n] = {Wf2[n][2k2],  Wg2[n][2k2],  Wf2[n][2k2+1], Wg2[n][2k2+1]}
// ---------------------------------------------------------------------------
__device__ float4 g_WA[KP][H_];
__device__ float4 g_WB[KP][H_];
__device__ float2 g_a0 [H_];          // time-row of fused A: {Af[j][0], Ag[j][0]}
__device__ float2 g_cfg[H_];          // {Wf1@b_in+bf1, Wg1@bn+bg1}
__device__ float2 g_b2 [H_];          // {bf2, bg2}

// ---------------------------------------------------------------------------
// Packed fp32x2 helpers (PTX-only dual-rate fp32 path).
// ---------------------------------------------------------------------------
typedef unsigned long long u64;
__device__ __forceinline__ void ffma2(u64& acc, u64 a, u64 b) {
    asm("fma.rn.f32x2 %0, %1, %2, %0;" : "+l"(acc) : "l"(a), "l"(b));
}
__device__ __forceinline__ u64 fadd2(u64 a, u64 b) {
    u64 r; asm("add.rn.f32x2 %0, %1, %2;" : "=l"(r) : "l"(a), "l"(b)); return r;
}
__device__ __forceinline__ u64 pack2(float lo, float hi) {
    u64 r;
    asm("mov.b64 %0, {%1, %2};" : "=l"(r)
        : "r"(__float_as_uint(lo)), "r"(__float_as_uint(hi)));
    return r;
}
__device__ __forceinline__ float lo2(u64 v) {
    return __uint_as_float((unsigned)(v & 0xffffffffull));
}
__device__ __forceinline__ float hi2(u64 v) {
    return __uint_as_float((unsigned)(v >> 32));
}
__device__ __forceinline__ u64 dup_lo(u64 v) { float f = lo2(v); return pack2(f, f); }
__device__ __forceinline__ u64 dup_hi(u64 v) { float f = hi2(v); return pack2(f, f); }
__device__ __forceinline__ float lipswish(float x) {
    return 0.909f * x / (1.0f + expf(-x));
}

// ---------------------------------------------------------------------------
// Prep 1: fuse the linear pairs; emit k-pair layout.
// ---------------------------------------------------------------------------
__global__ __launch_bounds__(256) void sde_prep_fuse(
    const float* __restrict__ W_in, const float* __restrict__ b_in,
    const float* __restrict__ Wf1,  const float* __restrict__ bf1,
    const float* __restrict__ Wn,   const float* __restrict__ bn,
    const float* __restrict__ Wg1,  const float* __restrict__ bg1)
{
    __shared__ float cin[H_], cn[H_];
    const int j = threadIdx.x;
    const int k = blockIdx.x;                 // 0..257
    if (k < H_ + 1) { cin[j] = W_in[j * (H_ + 1) + k]; cn[j] = Wn[j * (H_ + 1) + k]; }
    else            { cin[j] = b_in[j];                cn[j]  = bn[j]; }
    __syncthreads();
    const float* wf1r = Wf1 + (size_t)j * H_;
    const float* wg1r = Wg1 + (size_t)j * H_;
    float af = 0.f, ag = 0.f;
#pragma unroll 8
    for (int m = 0; m < H_; m++) {
        af = fmaf(wf1r[m], cin[m], af);
        ag = fmaf(wg1r[m], cn[m],  ag);
    }
    if (k == 0) {
        g_a0[j] = make_float2(af, ag);
    } else if (k <= H_) {
        const int k2 = (k - 1) >> 1, pos = (k - 1) & 1;
        float* p = reinterpret_cast<float*>(&g_WA[k2][j]);
        p[2 * pos] = af; p[2 * pos + 1] = ag;
    } else {
        g_cfg[j] = make_float2(af + bf1[j], ag + bg1[j]);
    }
}

// ---------------------------------------------------------------------------
// Prep 2: transpose second-layer weights into k-pair layout.
// ---------------------------------------------------------------------------
__global__ __launch_bounds__(256) void sde_prep_w2(
    const float* __restrict__ Wf2, const float* __restrict__ bf2,
    const float* __restrict__ Wg2, const float* __restrict__ bg2)
{
    const int n = threadIdx.x;
    const int k = blockIdx.x;                 // 0..255
    const int k2 = k >> 1, pos = k & 1;
    float* p = reinterpret_cast<float*>(&g_WB[k2][n]);
    p[2 * pos]     = Wf2[(size_t)n * H_ + k];
    p[2 * pos + 1] = Wg2[(size_t)n * H_ + k];
    if (k == 0) g_b2[n] = make_float2(bf2[n], bg2[n]);
}

// ---------------------------------------------------------------------------
// Main persistent kernel: 64 CTAs x 512 threads. Threads split into two
// k-halves (half = tid>>8); j = tid & 255. Each CTA: 4 batch rows, 999 steps.
// ---------------------------------------------------------------------------
__global__ __launch_bounds__(NTHR, 1) void sde_main(
    const float* __restrict__ coeffs, const float* __restrict__ times,
    const int*   __restrict__ mask,   const float* __restrict__ noise,
    const float* __restrict__ W0,     const float* __restrict__ b0,
    const float* __restrict__ Wd,     const float* __restrict__ bd,
    const float* __restrict__ Wc,     const float* __restrict__ bc,
    float* __restrict__ out)
{
    __shared__ float2 s_y01[H_];        // {y_row0, y_row1}[k]
    __shared__ float2 s_y23[H_];
    __shared__ float2 s_hfg[R_][H_];    // {hf_r, hg_r}[k]
    __shared__ ulonglong2 s_red[H_][2]; // cross-half partial accumulators
    __shared__ float4 s_part[8][DOUT];  // pred partials per 32-k chunk
    __shared__ float  s_zf[R_][H_];
    __shared__ float  s_tm[T_];
    __shared__ float  s_x0[R_][DIN];
    __shared__ int    s_len[R_];

    const int tid  = threadIdx.x;
    const int row0 = blockIdx.x * R_;
    const int j    = tid & 255;
    const int half = tid >> 8;
    const int kb2  = half * (KP / 2);       // this half's first k-pair

    // ---- init ----
    if (tid < R_) s_len[tid] = 0;
    for (int t = tid; t < T_; t += NTHR) s_tm[t] = times[t];
    if (tid < DIN) {
#pragma unroll
        for (int r = 0; r < R_; r++)
            s_x0[r][tid] = coeffs[(size_t)(row0 + r) * (size_t)(T_ - 1) * (4 * DIN) + tid];
    }
    __syncthreads();
    {
        int acc[R_] = {0, 0, 0, 0};
        for (int t = tid; t < T_; t += NTHR) {
#pragma unroll
            for (int r = 0; r < R_; r++) acc[r] += mask[(size_t)(row0 + r) * T_ + t];
        }
#pragma unroll
        for (int r = 0; r < R_; r++) atomicAdd(&s_len[r], acc[r]);
    }
    __syncthreads();
    int lastidx[R_];
#pragma unroll
    for (int r = 0; r < R_; r++) lastidx[r] = s_len[r] - 1;

    // ---- per-thread constants ----
    const float2 a0  = g_a0[j];
    const u64 p_af0 = pack2(a0.x, a0.x);
    const u64 p_ag0 = pack2(a0.y, a0.y);
    const float2 ccf = g_cfg[j];
    const float2 cb2 = g_b2[j];

    // Wd slice in registers: thread (pm = tid&63, pq = tid>>6 in 0..7) -> 32 k
    const int pm = tid & 63;
    const int pq = tid >> 6;
    float wdr[32];
    {
        const float* p = Wd + (size_t)pm * H_ + pq * 32;
#pragma unroll
        for (int kk = 0; kk < 32; kk++) wdr[kk] = p[kk];
    }
    const float bdv = bd[pm];

    // ---- y0 = x0 @ W0^T + b0 (half 0 owns the state) ----
    float y[R_] = {0.f, 0.f, 0.f, 0.f};
    float zfin[R_] = {0.f, 0.f, 0.f, 0.f};
    if (half == 0) {
        const float* w0r = W0 + (size_t)j * DIN;
        const float  bb  = b0[j];
#pragma unroll
        for (int r = 0; r < R_; r++) {
            float a = bb;
#pragma unroll 16
            for (int d = 0; d < DIN; d++) a = fmaf(s_x0[r][d], w0r[d], a);
            y[r] = a;
            zfin[r] = a;                       // covers lastidx == 0
        }
        s_y01[j] = make_float2(y[0], y[1]);
        s_y23[j] = make_float2(y[2], y[3]);
    }
    float t_cur = s_tm[0];
    __syncthreads();

    // ---- predicted[b][idx][:] = y @ Wd^T + bd ----
    auto do_pred = [&](int idx) {
        u64 a01 = 0ull, a23 = 0ull;
        const int kbase = pq * 32;             // k offset (float2 elements)
#pragma unroll
        for (int g = 0; g < 16; g++) {
            const ulonglong2 v01 = *reinterpret_cast<const ulonglong2*>(&s_y01[kbase + 2 * g]);
            const ulonglong2 v23 = *reinterpret_cast<const ulonglong2*>(&s_y23[kbase + 2 * g]);
            const u64 w0 = pack2(wdr[2 * g],     wdr[2 * g]);
            const u64 w1 = pack2(wdr[2 * g + 1], wdr[2 * g + 1]);
            ffma2(a01, v01.x, w0); ffma2(a01, v01.y, w1);
            ffma2(a23, v23.x, w0); ffma2(a23, v23.y, w1);
        }
        s_part[pq][pm] = make_float4(lo2(a01), hi2(a01), lo2(a23), hi2(a23));
        __syncthreads();
        if (tid < 256) {
            const int r2 = tid >> 6;
            float v = bdv;
#pragma unroll
            for (int qq = 0; qq < 8; qq++)
                v += reinterpret_cast<const float*>(&s_part[qq][pm])[r2];
            out[(size_t)(row0 + r2) * T_ * DOUT + (size_t)idx * DOUT + pm] = v;
        }
    };

    do_pred(0);

    // ======================= main scan: 999 steps =======================
    for (int i = 0; i < STEPS; i++) {
        // ---------- phase A: pre-act = A @ [t; y] ----------
        u64 af01, ag01, af23, ag23;
        if (half == 0) {
            const u64 tt = pack2(t_cur, t_cur);
            af01 = 0ull; ffma2(af01, tt, p_af0);
            ag01 = 0ull; ffma2(ag01, tt, p_ag0);
            af23 = af01; ag23 = ag01;
        } else { af01 = ag01 = af23 = ag23 = 0ull; }
        {
            const ulonglong2* wa =
                reinterpret_cast<const ulonglong2*>(&g_WA[kb2][0]) + j;
            ulonglong2 wbuf[4];
#pragma unroll
            for (int p = 0; p < 4; p++) wbuf[p] = wa[(size_t)p * H_];
#pragma unroll 1
            for (int blk = 0; blk < 16; blk++) {
                ulonglong2 wn[4];
                if (blk < 15) {
#pragma unroll
                    for (int p = 0; p < 4; p++)
                        wn[p] = wa[(size_t)(blk * 4 + 4 + p) * H_];
                }
#pragma unroll
                for (int p = 0; p < 4; p++) {
                    const int k2 = kb2 + blk * 4 + p;
                    const ulonglong2 v01 =
                        *reinterpret_cast<const ulonglong2*>(&s_y01[2 * k2]);
                    const ulonglong2 v23 =
                        *reinterpret_cast<const ulonglong2*>(&s_y23[2 * k2]);
                    const u64 df0 = dup_lo(wbuf[p].x), dg0 = dup_hi(wbuf[p].x);
                    const u64 df1 = dup_lo(wbuf[p].y), dg1 = dup_hi(wbuf[p].y);
                    ffma2(af01, v01.x, df0); ffma2(ag01, v01.x, dg0);
                    ffma2(af23, v23.x, df0); ffma2(ag23, v23.x, dg0);
                    ffma2(af01, v01.y, df1); ffma2(ag01, v01.y, dg1);
                    ffma2(af23, v23.y, df1); ffma2(ag23, v23.y, dg1);
                }
#pragma unroll
                for (int p = 0; p < 4; p++) wbuf[p] = wn[p];
            }
        }
        if (half == 1) {
            s_red[j][0] = make_ulonglong2(af01, ag01);
            s_red[j][1] = make_ulonglong2(af23, ag23);
        }
        __syncthreads();
        // prefetch noise (half 0)
        float eps[R_];
        if (half == 0) {
            const float* np = noise + ((size_t)i * B_ + row0) * H_ + j;
#pragma unroll
            for (int r = 0; r < R_; r++) eps[r] = __ldg(np + (size_t)r * H_);
        }
        if (half == 0) {
            const ulonglong2 q0 = s_red[j][0], q1 = s_red[j][1];
            af01 = fadd2(af01, q0.x); ag01 = fadd2(ag01, q0.y);
            af23 = fadd2(af23, q1.x); ag23 = fadd2(ag23, q1.y);
            const float hf0 = lipswish(lo2(af01) + ccf.x);
            const float hf1 = lipswish(hi2(af01) + ccf.x);
            const float hf2 = lipswish(lo2(af23) + ccf.x);
            const float hf3 = lipswish(hi2(af23) + ccf.x);
            const float hg0 = lipswish(lo2(ag01) + ccf.y);
            const float hg1 = lipswish(hi2(ag01) + ccf.y);
            const float hg2 = lipswish(lo2(ag23) + ccf.y);
            const float hg3 = lipswish(hi2(ag23) + ccf.y);
            s_hfg[0][j] = make_float2(hf0, hg0);
            s_hfg[1][j] = make_float2(hf1, hg1);
            s_hfg[2][j] = make_float2(hf2, hg2);
            s_hfg[3][j] = make_float2(hf3, hg3);
        }
        __syncthreads();

        // ---------- phase B: {f,g} = h @ W2 ----------
        u64 b0a = 0ull, b1a = 0ull, b2a = 0ull, b3a = 0ull;
        {
            const ulonglong2* wb =
                reinterpret_cast<const ulonglong2*>(&g_WB[kb2][0]) + j;
            ulonglong2 wbuf[4];
#pragma unroll
            for (int p = 0; p < 4; p++) wbuf[p] = wb[(size_t)p * H_];
#pragma unroll 1
            for (int blk = 0; blk < 16; blk++) {
                ulonglong2 wn[4];
                if (blk < 15) {
#pragma unroll
                    for (int p = 0; p < 4; p++)
                        wn[p] = wb[(size_t)(blk * 4 + 4 + p) * H_];
                }
#pragma unroll
                for (int p = 0; p < 4; p++) {
                    const int k2 = kb2 + blk * 4 + p;
                    const ulonglong2 h0 =
                        *reinterpret_cast<const ulonglong2*>(&s_hfg[0][2 * k2]);
                    const ulonglong2 h1 =
                        *reinterpret_cast<const ulonglong2*>(&s_hfg[1][2 * k2]);
                    const ulonglong2 h2 =
                        *reinterpret_cast<const ulonglong2*>(&s_hfg[2][2 * k2]);
                    const ulonglong2 h3 =
                        *reinterpret_cast<const ulonglong2*>(&s_hfg[3][2 * k2]);
                    ffma2(b0a, h0.x, wbuf[p].x); ffma2(b0a, h0.y, wbuf[p].y);
                    ffma2(b1a, h1.x, wbuf[p].x); ffma2(b1a, h1.y, wbuf[p].y);
                    ffma2(b2a, h2.x, wbuf[p].x); ffma2(b2a, h2.y, wbuf[p].y);
                    ffma2(b3a, h3.x, wbuf[p].x); ffma2(b3a, h3.y, wbuf[p].y);
                }
#pragma unroll
                for (int p = 0; p < 4; p++) wbuf[p] = wn[p];
            }
        }
        if (half == 1) {
            s_red[j][0] = make_ulonglong2(b0a, b1a);
            s_red[j][1] = make_ulonglong2(b2a, b3a);
        }
        __syncthreads();
        if (half == 0) {
            const ulonglong2 q0 = s_red[j][0], q1 = s_red[j][1];
            b0a = fadd2(b0a, q0.x); b1a = fadd2(b1a, q0.y);
            b2a = fadd2(b2a, q1.x); b3a = fadd2(b3a, q1.y);
            const float t_next = s_tm[i + 1];
            const float dt = t_next - t_cur;
            const float sd = sqrtf(dt);
            u64 fg[R_] = {b0a, b1a, b2a, b3a};
#pragma unroll
            for (int r = 0; r < R_; r++) {
                const float f = lo2(fg[r]) + cb2.x;
                const float g = hi2(fg[r]) + cb2.y;
                y[r] = fmaf(f, dt, fmaf(g, sd * eps[r], y[r]));
                if (i + 1 == lastidx[r]) zfin[r] = y[r];
            }
            s_y01[j] = make_float2(y[0], y[1]);
            s_y23[j] = make_float2(y[2], y[3]);
        }
        t_cur = s_tm[i + 1];
        __syncthreads();

        do_pred(i + 1);
    }

    // ---- logits = z_final @ Wc^T + bc ----
    if (half == 0) {
#pragma unroll
        for (int r = 0; r < R_; r++) s_zf[r][j] = zfin[r];
    }
    __syncthreads();
    if (tid < R_ * NC_) {
        const int r = tid / NC_;
        const int c = tid % NC_;
        const float* wcr = Wc + (size_t)c * H_;
        float a = bc[c];
#pragma unroll 8
        for (int k = 0; k < H_; k++) a = fmaf(s_zf[r][k], wcr[k], a);
        out[LOGITS_OFF + (size_t)(row0 + r) * NC_ + c] = a;
    }
}

// ---------------------------------------------------------------------------
// Launch: prep (fused weights) then the persistent scan. Stream-0 only,
// allocation-free, graph-capturable.
// ---------------------------------------------------------------------------
extern "C" void kernel_launch(void* const* d_in, const int* in_sizes, int n_in,
                              void* d_out, int out_size) {
    const float* coeffs = (const float*)d_in[0];
    const float* times  = (const float*)d_in[1];
    const int*   mask   = (const int*)  d_in[2];
    const float* noise  = (const float*)d_in[3];
    const float* W_in   = (const float*)d_in[4];
    const float* b_in   = (const float*)d_in[5];
    const float* Wf1    = (const float*)d_in[6];
    const float* bf1    = (const float*)d_in[7];
    const float* Wf2    = (const float*)d_in[8];
    const float* bf2    = (const float*)d_in[9];
    const float* Wn     = (const float*)d_in[10];
    const float* bn     = (const float*)d_in[11];
    const float* Wg1    = (const float*)d_in[12];
    const float* bg1    = (const float*)d_in[13];
    const float* Wg2    = (const float*)d_in[14];
    const float* bg2    = (const float*)d_in[15];
    const float* W0     = (const float*)d_in[16];
    const float* b0     = (const float*)d_in[17];
    const float* Wd     = (const float*)d_in[18];
    const float* bd     = (const float*)d_in[19];
    const float* Wc     = (const float*)d_in[20];
    const float* bc     = (const float*)d_in[21];
    float* out = (float*)d_out;

    sde_prep_fuse<<<H_ + 2, 256>>>(W_in, b_in, Wf1, bf1, Wn, bn, Wg1, bg1);
    sde_prep_w2  <<<H_,     256>>>(Wf2, bf2, Wg2, bg2);
    sde_main     <<<G_, NTHR>>>(coeffs, times, mask, noise,
                                W0, b0, Wd, bd, Wc, bc, out);
}